// round 9
// baseline (speedup 1.0000x reference)
#include <cuda_runtime.h>
#include <math.h>

#define Bsz 2
#define T 2048
#define D 1024
#define H 16
#define DH 64
#define F 4096
#define BT (Bsz * T)

// ---------------- scratch (device globals: no runtime allocation allowed) ----
__device__ __align__(16) float g_qin[(size_t)BT * D];            //  16 MB
__device__ __align__(16) float g_qkv[(size_t)BT * 3 * D];        //  48 MB
__device__ __align__(16) float g_scores[(size_t)Bsz * H * T * T];// 512 MB (reused in-place for probs)
__device__ __align__(16) float g_y[(size_t)BT * D];              //  16 MB
__device__ __align__(16) float g_x2[(size_t)BT * D];             //  16 MB
__device__ __align__(16) float g_hln[(size_t)BT * D];            //  16 MB
__device__ __align__(16) float g_col1[(size_t)BT * D * 3];       //  50 MB
__device__ __align__(16) float g_h1[(size_t)BT * F];             //  67 MB
__device__ __align__(16) float g_col2[(size_t)BT * F * 3];       // 201 MB
__device__ int g_mask_is_word;  // 1 if mask elements are 4-byte (int32/float32), 0 if 1-byte

// ---------------- reductions ------------------------------------------------
__device__ __forceinline__ float warpSum(float v) {
#pragma unroll
    for (int o = 16; o > 0; o >>= 1) v += __shfl_xor_sync(0xffffffffu, v, o);
    return v;
}
__device__ __forceinline__ float warpMax(float v) {
#pragma unroll
    for (int o = 16; o > 0; o >>= 1) v = fmaxf(v, __shfl_xor_sync(0xffffffffu, v, o));
    return v;
}

// ---------------- mask dtype detection --------------------------------------
// Flat idx 3584 = (b=1, s=1536) -> true (==1) if 1-byte layout.
// If elements are 4-byte, byte 3584 is byte 0 of element 896 (b=0,s=896) -> 0.
__global__ void detect_mask_kernel(const unsigned char* __restrict__ p) {
    g_mask_is_word = (p[3584] == 0) ? 1 : 0;
}

// ---------------- LayerNorm (+ optional positional add) ---------------------
__global__ void ln_kernel(const float* __restrict__ x,
                          const float* __restrict__ gw,
                          const float* __restrict__ bw,
                          const float* __restrict__ pos,  // may be null
                          float* __restrict__ out) {
    int row = blockIdx.x;           // b*T + t
    int t = row & (T - 1);
    int tid = threadIdx.x;          // 256 threads, D=1024 -> 4 elems each
    const float* xr = x + (size_t)row * D;
    float v[4];
    float s = 0.f, sq = 0.f;
#pragma unroll
    for (int i = 0; i < 4; i++) {
        v[i] = xr[tid + i * 256];
        s += v[i];
        sq += v[i] * v[i];
    }
    __shared__ float sh[16];
    s = warpSum(s);
    sq = warpSum(sq);
    int lane = tid & 31, wid = tid >> 5;
    if (lane == 0) { sh[wid] = s; sh[wid + 8] = sq; }
    __syncthreads();
    if (wid == 0) {
        float a = (lane < 8) ? sh[lane] : 0.f;
        float c = (lane < 8) ? sh[lane + 8] : 0.f;
        a = warpSum(a);
        c = warpSum(c);
        if (lane == 0) { sh[0] = a; sh[1] = c; }
    }
    __syncthreads();
    float mu = sh[0] * (1.f / D);
    float var = sh[1] * (1.f / D) - mu * mu;
    float rstd = rsqrtf(fmaxf(var, 0.f) + 1e-5f);
    float* orow = out + (size_t)row * D;
#pragma unroll
    for (int i = 0; i < 4; i++) {
        int d = tid + i * 256;
        float o = (v[i] - mu) * rstd * gw[d] + bw[d];
        if (pos) o += pos[(size_t)t * D + d];
        orow[d] = o;
    }
}

// ---------------- SGEMM  C[m,n] = sum_k A[m,k]*B[n,k] (+ optional R) --------
#define BM 128
#define BN 128
#define BK 8

__device__ __forceinline__ void gemm_nt_body(
    const float* __restrict__ A, int lda,
    const float* __restrict__ B, int ldb,
    const float* __restrict__ R,   // residual, same layout as C (may be null)
    float* __restrict__ C, int ldc,
    int K, int m0, int n0)
{
    __shared__ float As[BK][BM + 4];
    __shared__ float Bs[BK][BN + 4];
    int tid = threadIdx.x;            // 256
    int tx = tid & 15, ty = tid >> 4; // 16x16; each thread: 8x8 microtile
    int lrow = tid >> 1;              // 0..127
    int lcol = (tid & 1) * 4;         // 0 or 4
    const float* Ap = A + (size_t)(m0 + lrow) * lda + lcol;
    const float* Bp = B + (size_t)(n0 + lrow) * ldb + lcol;

    float acc[8][8];
#pragma unroll
    for (int i = 0; i < 8; i++)
#pragma unroll
        for (int j = 0; j < 8; j++) acc[i][j] = 0.f;

    for (int k0 = 0; k0 < K; k0 += BK) {
        float4 av = *(const float4*)(Ap + k0);
        float4 bv = *(const float4*)(Bp + k0);
        As[lcol + 0][lrow] = av.x; As[lcol + 1][lrow] = av.y;
        As[lcol + 2][lrow] = av.z; As[lcol + 3][lrow] = av.w;
        Bs[lcol + 0][lrow] = bv.x; Bs[lcol + 1][lrow] = bv.y;
        Bs[lcol + 2][lrow] = bv.z; Bs[lcol + 3][lrow] = bv.w;
        __syncthreads();
#pragma unroll
        for (int kk = 0; kk < BK; kk++) {
            float a[8], b[8];
#pragma unroll
            for (int i = 0; i < 8; i++) a[i] = As[kk][ty * 8 + i];
#pragma unroll
            for (int j = 0; j < 8; j++) b[j] = Bs[kk][tx * 8 + j];
#pragma unroll
            for (int i = 0; i < 8; i++)
#pragma unroll
                for (int j = 0; j < 8; j++)
                    acc[i][j] = fmaf(a[i], b[j], acc[i][j]);
        }
        __syncthreads();
    }
#pragma unroll
    for (int i = 0; i < 8; i++) {
        size_t cr = (size_t)(m0 + ty * 8 + i) * ldc + n0 + tx * 8;
#pragma unroll
        for (int j = 0; j < 8; j++) {
            float v = acc[i][j];
            if (R) v += R[cr + j];
            C[cr + j] = v;
        }
    }
}

__global__ void gemm_nt_kernel(const float* A, int lda, const float* B, int ldb,
                               const float* R, float* C, int ldc, int K) {
    gemm_nt_body(A, lda, B, ldb, R, C, ldc, K, blockIdx.y * BM, blockIdx.x * BN);
}

// ---------------- attention: raw scores (pure GEMM, masked tiles skipped) ---
__global__ void scores_kernel(const float* __restrict__ qkv) {
    int z = blockIdx.z, b = z >> 4, h = z & 15;
    int m0 = blockIdx.y * BM, n0 = blockIdx.x * BN;
    if (n0 > m0) return;  // tile entirely above causal diagonal -> softmax masks it
    const float* q = qkv + (size_t)b * T * 3 * D + h * DH;
    const float* k = q + D;       // sel=1
    float* Cp = g_scores + (size_t)z * T * T;
    gemm_nt_body(q, 3 * D, k, 3 * D, nullptr, Cp, T, DH, m0, n0);
}

// ---------------- softmax ----------------------------------------------------
// Reference semantics: pad_mask broadcasts over the QUERY axis (keys are only
// causally bounded). A padded query row t yields an all-zero prob row.
// Only s < slimit = (floor(t/128)+1)*128 is ever read by pv_kernel, so we only
// write that range.
__global__ void softmax_kernel(const void* __restrict__ maskp) {
    int row = blockIdx.x;           // z*T + t
    int t = row & (T - 1);
    int b = row >> 15;              // row / (H*T), H*T = 32768
    float* sr = g_scores + (size_t)row * T;
    int tid = threadIdx.x;          // 256
    int slimit = ((t >> 7) + 1) << 7;   // covers causal extent, multiple of 128
    const float scale = 0.125f;     // dh^-0.5
    bool word = (g_mask_is_word != 0);
    bool padded = word ? (((const int*)maskp)[b * T + t] != 0)
                       : (((const unsigned char*)maskp)[b * T + t] != 0);
    if (padded) {
        // reference: prob row is exactly zero for padded query positions
        for (int s = tid; s < slimit; s += 256) sr[s] = 0.f;
        return;
    }
    float v[8];
    float m = -1e30f;
#pragma unroll
    for (int i = 0; i < 8; i++) {
        int s = tid + i * 256;
        float val = -1e30f;                   // s >= slimit: inert, never written
        if (s < slimit) val = (s > t) ? -1e9f : sr[s] * scale;
        v[i] = val;
        m = fmaxf(m, val);
    }
    __shared__ float sh[8];
    __shared__ float bc;
    m = warpMax(m);
    int lane = tid & 31, wid = tid >> 5;
    if (lane == 0) sh[wid] = m;
    __syncthreads();
    if (wid == 0) {
        float a = (lane < 8) ? sh[lane] : -1e30f;
        a = warpMax(a);
        if (lane == 0) bc = a;
    }
    __syncthreads();
    float M = bc;
    float sum = 0.f;
#pragma unroll
    for (int i = 0; i < 8; i++) {
        float e = __expf(v[i] - M);  // masked -> flushes to exactly 0
        v[i] = e;
        sum += e;
    }
    __syncthreads();
    sum = warpSum(sum);
    if (lane == 0) sh[wid] = sum;
    __syncthreads();
    if (wid == 0) {
        float a = (lane < 8) ? sh[lane] : 0.f;
        a = warpSum(a);
        if (lane == 0) bc = a;
    }
    __syncthreads();
    float inv = 1.f / bc;
#pragma unroll
    for (int i = 0; i < 8; i++) {
        int s = tid + i * 256;
        if (s < slimit) sr[s] = v[i] * inv;
    }
}

// ---------------- PV: y[t,d] = sum_s prob[t,s] * v[s,d]  (causal K limit) ---
#define PVM 128
#define PVN 64
#define PVK 16
__global__ void pv_kernel(const float* __restrict__ qkv, float* __restrict__ y) {
    int z = blockIdx.z, b = z >> 4, h = z & 15;
    const float* P = g_scores + (size_t)z * T * T;             // probs (in-place)
    const float* V = qkv + (size_t)b * T * 3 * D + 2 * D + h * DH;
    float* C = y + (size_t)b * T * D + h * DH;
    int m0 = blockIdx.y * PVM;

    __shared__ float Ps[PVK][PVM + 4];
    __shared__ float Vs[PVK][PVN + 4];
    int tid = threadIdx.x;             // 256
    int tx = tid & 15, ty = tid >> 4;  // microtile 8 rows x 4 cols
    int prow = tid >> 1, pc = (tid & 1) * 8;
    int vk = tid >> 4, vn = (tid & 15) * 4;

    float acc[8][4];
#pragma unroll
    for (int i = 0; i < 8; i++)
#pragma unroll
        for (int j = 0; j < 4; j++) acc[i][j] = 0.f;

    int Klim = m0 + PVM;  // prob[t,s]==0 for s>t, rows here have t < m0+PVM
    for (int k0 = 0; k0 < Klim; k0 += PVK) {
        const float* pr = P + (size_t)(m0 + prow) * T + k0 + pc;
        float4 p0 = *(const float4*)pr;
        float4 p1 = *(const float4*)(pr + 4);
        Ps[pc + 0][prow] = p0.x; Ps[pc + 1][prow] = p0.y;
        Ps[pc + 2][prow] = p0.z; Ps[pc + 3][prow] = p0.w;
        Ps[pc + 4][prow] = p1.x; Ps[pc + 5][prow] = p1.y;
        Ps[pc + 6][prow] = p1.z; Ps[pc + 7][prow] = p1.w;
        float4 vv = *(const float4*)(V + (size_t)(k0 + vk) * (3 * D) + vn);
        Vs[vk][vn + 0] = vv.x; Vs[vk][vn + 1] = vv.y;
        Vs[vk][vn + 2] = vv.z; Vs[vk][vn + 3] = vv.w;
        __syncthreads();
#pragma unroll
        for (int kk = 0; kk < PVK; kk++) {
            float a[8], bb[4];
#pragma unroll
            for (int i = 0; i < 8; i++) a[i] = Ps[kk][ty * 8 + i];
#pragma unroll
            for (int j = 0; j < 4; j++) bb[j] = Vs[kk][tx * 4 + j];
#pragma unroll
            for (int i = 0; i < 8; i++)
#pragma unroll
                for (int j = 0; j < 4; j++)
                    acc[i][j] = fmaf(a[i], bb[j], acc[i][j]);
        }
        __syncthreads();
    }
#pragma unroll
    for (int i = 0; i < 8; i++) {
        size_t cr = (size_t)(m0 + ty * 8 + i) * D + tx * 4;
#pragma unroll
        for (int j = 0; j < 4; j++) C[cr + j] = acc[i][j];
    }
}

// ---------------- im2col for causal K=3 conv (left pad 2) -------------------
// dst[(b*T+t)*C*3 + c*3 + k] = src[(b*T + t+k-2)*C + c]  (0 if t+k-2 < 0)
__global__ void im2col_k3(const float* __restrict__ src, float* __restrict__ dst,
                          int C, int total) {
    int idx = blockIdx.x * 256 + threadIdx.x;
    if (idx >= total) return;
    int k = idx % 3;
    int rem = idx / 3;
    int c = rem % C;
    int row = rem / C;        // b*T + t
    int t = row & (T - 1);
    int ts = t + k - 2;
    dst[idx] = (ts >= 0) ? src[(size_t)(row + k - 2) * C + c] : 0.f;
}

// ---------------- gelu (tanh approx), in-place ------------------------------
__global__ void gelu_kernel(float* __restrict__ h, int n) {
    int i = blockIdx.x * 256 + threadIdx.x;
    if (i >= n) return;
    float x = h[i];
    float u = 0.7978845608028654f * (x + 0.044715f * x * x * x);
    h[i] = 0.5f * x * (1.0f + tanhf(u));
}

// ---------------- launch ----------------------------------------------------
extern "C" void kernel_launch(void* const* d_in, const int* in_sizes, int n_in,
                              void* d_out, int out_size) {
    const float* x     = (const float*)d_in[0];
    const void*  mask  = d_in[1];
    const float* pos   = (const float*)d_in[2];
    const float* w_qkv = (const float*)d_in[3];
    const float* w_o   = (const float*)d_in[4];
    const float* ln1g  = (const float*)d_in[5];
    const float* ln1b  = (const float*)d_in[6];
    const float* ln2g  = (const float*)d_in[7];
    const float* ln2b  = (const float*)d_in[8];
    const float* w1    = (const float*)d_in[9];   // (F, D, 3) contiguous -> [F, 3D] flat
    const float* w2    = (const float*)d_in[10];  // (D, F, 3) contiguous -> [D, 3F] flat
    float* out = (float*)d_out;

    float *qin, *qkv, *y, *x2, *hln, *col1, *h1, *col2;
    cudaGetSymbolAddress((void**)&qin,  g_qin);
    cudaGetSymbolAddress((void**)&qkv,  g_qkv);
    cudaGetSymbolAddress((void**)&y,    g_y);
    cudaGetSymbolAddress((void**)&x2,   g_x2);
    cudaGetSymbolAddress((void**)&hln,  g_hln);
    cudaGetSymbolAddress((void**)&col1, g_col1);
    cudaGetSymbolAddress((void**)&h1,   g_h1);
    cudaGetSymbolAddress((void**)&col2, g_col2);

    // 0. mask dtype probe
    detect_mask_kernel<<<1, 1>>>((const unsigned char*)mask);
    // 1. LN1 + positional
    ln_kernel<<<BT, 256>>>(x, ln1g, ln1b, pos, qin);
    // 2. QKV projection: (4096 x 3072 x 1024)
    gemm_nt_kernel<<<dim3(3 * D / BN, BT / BM), 256>>>(qin, D, w_qkv, D, nullptr, qkv, 3 * D, D);
    // 3. scores = Q K^T (batched over b,h; upper-causal tiles skipped)
    scores_kernel<<<dim3(T / BN, T / BM, Bsz * H), 256>>>(qkv);
    // 4. softmax: causal mask over keys; padded QUERY rows -> zero prob rows
    softmax_kernel<<<Bsz * H * T, 256>>>(mask);
    // 5. y = P V (batched, causal K limit)
    pv_kernel<<<dim3(1, T / PVM, Bsz * H), 256>>>(qkv, y);
    // 6. x2 = x + y W_o^T
    gemm_nt_kernel<<<dim3(D / BN, BT / BM), 256>>>(y, D, w_o, D, x, x2, D, D);
    // 7. LN2
    ln_kernel<<<BT, 256>>>(x2, ln2g, ln2b, nullptr, hln);
    // 8. conv1 via im2col + GEMM (4096 x 4096 x 3072)
    im2col_k3<<<(BT * D * 3 + 255) / 256, 256>>>(hln, col1, D, BT * D * 3);
    gemm_nt_kernel<<<dim3(F / BN, BT / BM), 256>>>(col1, 3 * D, w1, 3 * D, nullptr, h1, F, 3 * D);
    // 9. gelu
    gelu_kernel<<<(BT * F + 255) / 256, 256>>>(h1, BT * F);
    // 10. conv2 via im2col + GEMM (4096 x 1024 x 12288), fused final residual
    im2col_k3<<<(BT * F * 3 + 255) / 256, 256>>>(h1, col2, F, BT * F * 3);
    gemm_nt_kernel<<<dim3(D / BN, BT / BM), 256>>>(col2, 3 * F, w2, 3 * F, x2, out, D, 3 * F);
}

// round 10
// speedup vs baseline: 1.0017x; 1.0017x over previous
#include <cuda_runtime.h>
#include <math.h>

#define Bsz 2
#define T 2048
#define D 1024
#define H 16
#define DH 64
#define F 4096
#define BT (Bsz * T)

// ---------------- scratch (device globals: no runtime allocation allowed) ----
__device__ __align__(16) float g_qin[(size_t)BT * D];            //  16 MB
__device__ __align__(16) float g_qkv[(size_t)BT * 3 * D];        //  48 MB
__device__ __align__(16) float g_scores[(size_t)Bsz * H * T * T];// 512 MB (reused in-place for probs)
__device__ __align__(16) float g_y[(size_t)BT * D];              //  16 MB
__device__ __align__(16) float g_x2[(size_t)BT * D];             //  16 MB
__device__ __align__(16) float g_hln[(size_t)BT * D];            //  16 MB
__device__ __align__(16) float g_col1[(size_t)BT * D * 3];       //  50 MB
__device__ __align__(16) float g_h1[(size_t)BT * F];             //  67 MB
__device__ __align__(16) float g_col2[(size_t)BT * F * 3];       // 201 MB
__device__ int g_mask_is_word;  // 1 if mask elements are 4-byte (int32/float32), 0 if 1-byte

// ---------------- reductions ------------------------------------------------
__device__ __forceinline__ float warpSum(float v) {
#pragma unroll
    for (int o = 16; o > 0; o >>= 1) v += __shfl_xor_sync(0xffffffffu, v, o);
    return v;
}
__device__ __forceinline__ float warpMax(float v) {
#pragma unroll
    for (int o = 16; o > 0; o >>= 1) v = fmaxf(v, __shfl_xor_sync(0xffffffffu, v, o));
    return v;
}

// ---------------- mask dtype detection --------------------------------------
// Flat idx 3584 = (b=1, s=1536) -> true (==1) if 1-byte layout.
// If elements are 4-byte, byte 3584 is byte 0 of element 896 (b=0,s=896) -> 0.
__global__ void detect_mask_kernel(const unsigned char* __restrict__ p) {
    g_mask_is_word = (p[3584] == 0) ? 1 : 0;
}

// ---------------- LayerNorm (+ optional positional add) ---------------------
__global__ void ln_kernel(const float* __restrict__ x,
                          const float* __restrict__ gw,
                          const float* __restrict__ bw,
                          const float* __restrict__ pos,  // may be null
                          float* __restrict__ out) {
    int row = blockIdx.x;           // b*T + t
    int t = row & (T - 1);
    int tid = threadIdx.x;          // 256 threads, D=1024 -> 4 elems each
    const float* xr = x + (size_t)row * D;
    float v[4];
    float s = 0.f, sq = 0.f;
#pragma unroll
    for (int i = 0; i < 4; i++) {
        v[i] = xr[tid + i * 256];
        s += v[i];
        sq += v[i] * v[i];
    }
    __shared__ float sh[16];
    s = warpSum(s);
    sq = warpSum(sq);
    int lane = tid & 31, wid = tid >> 5;
    if (lane == 0) { sh[wid] = s; sh[wid + 8] = sq; }
    __syncthreads();
    if (wid == 0) {
        float a = (lane < 8) ? sh[lane] : 0.f;
        float c = (lane < 8) ? sh[lane + 8] : 0.f;
        a = warpSum(a);
        c = warpSum(c);
        if (lane == 0) { sh[0] = a; sh[1] = c; }
    }
    __syncthreads();
    float mu = sh[0] * (1.f / D);
    float var = sh[1] * (1.f / D) - mu * mu;
    float rstd = rsqrtf(fmaxf(var, 0.f) + 1e-5f);
    float* orow = out + (size_t)row * D;
#pragma unroll
    for (int i = 0; i < 4; i++) {
        int d = tid + i * 256;
        float o = (v[i] - mu) * rstd * gw[d] + bw[d];
        if (pos) o += pos[(size_t)t * D + d];
        orow[d] = o;
    }
}

// ---------------- SGEMM  C[m,n] = sum_k A[m,k]*B[n,k] (+ optional R) --------
#define BM 128
#define BN 128
#define BK 8

__device__ __forceinline__ void gemm_nt_body(
    const float* __restrict__ A, int lda,
    const float* __restrict__ B, int ldb,
    const float* __restrict__ R,   // residual, same layout as C (may be null)
    float* __restrict__ C, int ldc,
    int K, int m0, int n0)
{
    __shared__ float As[BK][BM + 4];
    __shared__ float Bs[BK][BN + 4];
    int tid = threadIdx.x;            // 256
    int tx = tid & 15, ty = tid >> 4; // 16x16; each thread: 8x8 microtile
    int lrow = tid >> 1;              // 0..127
    int lcol = (tid & 1) * 4;         // 0 or 4
    const float* Ap = A + (size_t)(m0 + lrow) * lda + lcol;
    const float* Bp = B + (size_t)(n0 + lrow) * ldb + lcol;

    float acc[8][8];
#pragma unroll
    for (int i = 0; i < 8; i++)
#pragma unroll
        for (int j = 0; j < 8; j++) acc[i][j] = 0.f;

    for (int k0 = 0; k0 < K; k0 += BK) {
        float4 av = *(const float4*)(Ap + k0);
        float4 bv = *(const float4*)(Bp + k0);
        As[lcol + 0][lrow] = av.x; As[lcol + 1][lrow] = av.y;
        As[lcol + 2][lrow] = av.z; As[lcol + 3][lrow] = av.w;
        Bs[lcol + 0][lrow] = bv.x; Bs[lcol + 1][lrow] = bv.y;
        Bs[lcol + 2][lrow] = bv.z; Bs[lcol + 3][lrow] = bv.w;
        __syncthreads();
#pragma unroll
        for (int kk = 0; kk < BK; kk++) {
            float a[8], b[8];
#pragma unroll
            for (int i = 0; i < 8; i++) a[i] = As[kk][ty * 8 + i];
#pragma unroll
            for (int j = 0; j < 8; j++) b[j] = Bs[kk][tx * 8 + j];
#pragma unroll
            for (int i = 0; i < 8; i++)
#pragma unroll
                for (int j = 0; j < 8; j++)
                    acc[i][j] = fmaf(a[i], b[j], acc[i][j]);
        }
        __syncthreads();
    }
#pragma unroll
    for (int i = 0; i < 8; i++) {
        size_t cr = (size_t)(m0 + ty * 8 + i) * ldc + n0 + tx * 8;
#pragma unroll
        for (int j = 0; j < 8; j++) {
            float v = acc[i][j];
            if (R) v += R[cr + j];
            C[cr + j] = v;
        }
    }
}

__global__ void gemm_nt_kernel(const float* A, int lda, const float* B, int ldb,
                               const float* R, float* C, int ldc, int K) {
    gemm_nt_body(A, lda, B, ldb, R, C, ldc, K, blockIdx.y * BM, blockIdx.x * BN);
}

// ---------------- attention: raw scores (pure GEMM, masked tiles skipped) ---
__global__ void scores_kernel(const float* __restrict__ qkv) {
    int z = blockIdx.z, b = z >> 4, h = z & 15;
    int m0 = blockIdx.y * BM, n0 = blockIdx.x * BN;
    if (n0 > m0) return;  // tile entirely above causal diagonal -> softmax masks it
    const float* q = qkv + (size_t)b * T * 3 * D + h * DH;
    const float* k = q + D;       // sel=1
    float* Cp = g_scores + (size_t)z * T * T;
    gemm_nt_body(q, 3 * D, k, 3 * D, nullptr, Cp, T, DH, m0, n0);
}

// ---------------- softmax ----------------------------------------------------
// Reference semantics: pad_mask broadcasts over the QUERY axis (keys are only
// causally bounded). A padded query row t yields an all-zero prob row.
// Only s < slimit = (floor(t/128)+1)*128 is ever read by pv_kernel, so we only
// write that range.
__global__ void softmax_kernel(const void* __restrict__ maskp) {
    int row = blockIdx.x;           // z*T + t
    int t = row & (T - 1);
    int b = row >> 15;              // row / (H*T), H*T = 32768
    float* sr = g_scores + (size_t)row * T;
    int tid = threadIdx.x;          // 256
    int slimit = ((t >> 7) + 1) << 7;   // covers causal extent, multiple of 128
    const float scale = 0.125f;     // dh^-0.5
    bool word = (g_mask_is_word != 0);
    bool padded = word ? (((const int*)maskp)[b * T + t] != 0)
                       : (((const unsigned char*)maskp)[b * T + t] != 0);
    if (padded) {
        // reference: prob row is exactly zero for padded query positions
        for (int s = tid; s < slimit; s += 256) sr[s] = 0.f;
        return;
    }
    float v[8];
    float m = -1e30f;
#pragma unroll
    for (int i = 0; i < 8; i++) {
        int s = tid + i * 256;
        float val = -1e30f;                   // s >= slimit: inert, never written
        if (s < slimit) val = (s > t) ? -1e9f : sr[s] * scale;
        v[i] = val;
        m = fmaxf(m, val);
    }
    __shared__ float sh[8];
    __shared__ float bc;
    m = warpMax(m);
    int lane = tid & 31, wid = tid >> 5;
    if (lane == 0) sh[wid] = m;
    __syncthreads();
    if (wid == 0) {
        float a = (lane < 8) ? sh[lane] : -1e30f;
        a = warpMax(a);
        if (lane == 0) bc = a;
    }
    __syncthreads();
    float M = bc;
    float sum = 0.f;
#pragma unroll
    for (int i = 0; i < 8; i++) {
        float e = __expf(v[i] - M);  // masked -> flushes to exactly 0
        v[i] = e;
        sum += e;
    }
    __syncthreads();
    sum = warpSum(sum);
    if (lane == 0) sh[wid] = sum;
    __syncthreads();
    if (wid == 0) {
        float a = (lane < 8) ? sh[lane] : 0.f;
        a = warpSum(a);
        if (lane == 0) bc = a;
    }
    __syncthreads();
    float inv = 1.f / bc;
#pragma unroll
    for (int i = 0; i < 8; i++) {
        int s = tid + i * 256;
        if (s < slimit) sr[s] = v[i] * inv;
    }
}

// ---------------- PV: y[t,d] = sum_s prob[t,s] * v[s,d]  (causal K limit) ---
#define PVM 128
#define PVN 64
#define PVK 16
__global__ void pv_kernel(const float* __restrict__ qkv, float* __restrict__ y) {
    int z = blockIdx.z, b = z >> 4, h = z & 15;
    const float* P = g_scores + (size_t)z * T * T;             // probs (in-place)
    const float* V = qkv + (size_t)b * T * 3 * D + 2 * D + h * DH;
    float* C = y + (size_t)b * T * D + h * DH;
    int m0 = blockIdx.y * PVM;

    __shared__ float Ps[PVK][PVM + 4];
    __shared__ float Vs[PVK][PVN + 4];
    int tid = threadIdx.x;             // 256
    int tx = tid & 15, ty = tid >> 4;  // microtile 8 rows x 4 cols
    int prow = tid >> 1, pc = (tid & 1) * 8;
    int vk = tid >> 4, vn = (tid & 15) * 4;

    float acc[8][4];
#pragma unroll
    for (int i = 0; i < 8; i++)
#pragma unroll
        for (int j = 0; j < 4; j++) acc[i][j] = 0.f;

    int Klim = m0 + PVM;  // prob[t,s]==0 for s>t, rows here have t < m0+PVM
    for (int k0 = 0; k0 < Klim; k0 += PVK) {
        const float* pr = P + (size_t)(m0 + prow) * T + k0 + pc;
        float4 p0 = *(const float4*)pr;
        float4 p1 = *(const float4*)(pr + 4);
        Ps[pc + 0][prow] = p0.x; Ps[pc + 1][prow] = p0.y;
        Ps[pc + 2][prow] = p0.z; Ps[pc + 3][prow] = p0.w;
        Ps[pc + 4][prow] = p1.x; Ps[pc + 5][prow] = p1.y;
        Ps[pc + 6][prow] = p1.z; Ps[pc + 7][prow] = p1.w;
        float4 vv = *(const float4*)(V + (size_t)(k0 + vk) * (3 * D) + vn);
        Vs[vk][vn + 0] = vv.x; Vs[vk][vn + 1] = vv.y;
        Vs[vk][vn + 2] = vv.z; Vs[vk][vn + 3] = vv.w;
        __syncthreads();
#pragma unroll
        for (int kk = 0; kk < PVK; kk++) {
            float a[8], bb[4];
#pragma unroll
            for (int i = 0; i < 8; i++) a[i] = Ps[kk][ty * 8 + i];
#pragma unroll
            for (int j = 0; j < 4; j++) bb[j] = Vs[kk][tx * 4 + j];
#pragma unroll
            for (int i = 0; i < 8; i++)
#pragma unroll
                for (int j = 0; j < 4; j++)
                    acc[i][j] = fmaf(a[i], bb[j], acc[i][j]);
        }
        __syncthreads();
    }
#pragma unroll
    for (int i = 0; i < 8; i++) {
        size_t cr = (size_t)(m0 + ty * 8 + i) * D + tx * 4;
#pragma unroll
        for (int j = 0; j < 4; j++) C[cr + j] = acc[i][j];
    }
}

// ---------------- im2col for causal K=3 conv (left pad 2) -------------------
// dst[(b*T+t)*C*3 + c*3 + k] = src[(b*T + t+k-2)*C + c]  (0 if t+k-2 < 0)
__global__ void im2col_k3(const float* __restrict__ src, float* __restrict__ dst,
                          int C, int total) {
    int idx = blockIdx.x * 256 + threadIdx.x;
    if (idx >= total) return;
    int k = idx % 3;
    int rem = idx / 3;
    int c = rem % C;
    int row = rem / C;        // b*T + t
    int t = row & (T - 1);
    int ts = t + k - 2;
    dst[idx] = (ts >= 0) ? src[(size_t)(row + k - 2) * C + c] : 0.f;
}

// ---------------- gelu (tanh approx), in-place ------------------------------
__global__ void gelu_kernel(float* __restrict__ h, int n) {
    int i = blockIdx.x * 256 + threadIdx.x;
    if (i >= n) return;
    float x = h[i];
    float u = 0.7978845608028654f * (x + 0.044715f * x * x * x);
    h[i] = 0.5f * x * (1.0f + tanhf(u));
}

// ---------------- launch ----------------------------------------------------
extern "C" void kernel_launch(void* const* d_in, const int* in_sizes, int n_in,
                              void* d_out, int out_size) {
    const float* x     = (const float*)d_in[0];
    const void*  mask  = d_in[1];
    const float* pos   = (const float*)d_in[2];
    const float* w_qkv = (const float*)d_in[3];
    const float* w_o   = (const float*)d_in[4];
    const float* ln1g  = (const float*)d_in[5];
    const float* ln1b  = (const float*)d_in[6];
    const float* ln2g  = (const float*)d_in[7];
    const float* ln2b  = (const float*)d_in[8];
    const float* w1    = (const float*)d_in[9];   // (F, D, 3) contiguous -> [F, 3D] flat
    const float* w2    = (const float*)d_in[10];  // (D, F, 3) contiguous -> [D, 3F] flat
    float* out = (float*)d_out;

    float *qin, *qkv, *y, *x2, *hln, *col1, *h1, *col2;
    cudaGetSymbolAddress((void**)&qin,  g_qin);
    cudaGetSymbolAddress((void**)&qkv,  g_qkv);
    cudaGetSymbolAddress((void**)&y,    g_y);
    cudaGetSymbolAddress((void**)&x2,   g_x2);
    cudaGetSymbolAddress((void**)&hln,  g_hln);
    cudaGetSymbolAddress((void**)&col1, g_col1);
    cudaGetSymbolAddress((void**)&h1,   g_h1);
    cudaGetSymbolAddress((void**)&col2, g_col2);

    // 0. mask dtype probe
    detect_mask_kernel<<<1, 1>>>((const unsigned char*)mask);
    // 1. LN1 + positional
    ln_kernel<<<BT, 256>>>(x, ln1g, ln1b, pos, qin);
    // 2. QKV projection: (4096 x 3072 x 1024)
    gemm_nt_kernel<<<dim3(3 * D / BN, BT / BM), 256>>>(qin, D, w_qkv, D, nullptr, qkv, 3 * D, D);
    // 3. scores = Q K^T (batched over b,h; upper-causal tiles skipped)
    scores_kernel<<<dim3(T / BN, T / BM, Bsz * H), 256>>>(qkv);
    // 4. softmax: causal mask over keys; padded QUERY rows -> zero prob rows
    softmax_kernel<<<Bsz * H * T, 256>>>(mask);
    // 5. y = P V (batched, causal K limit)
    pv_kernel<<<dim3(1, T / PVM, Bsz * H), 256>>>(qkv, y);
    // 6. x2 = x + y W_o^T
    gemm_nt_kernel<<<dim3(D / BN, BT / BM), 256>>>(y, D, w_o, D, x, x2, D, D);
    // 7. LN2
    ln_kernel<<<BT, 256>>>(x2, ln2g, ln2b, nullptr, hln);
    // 8. conv1 via im2col + GEMM (4096 x 4096 x 3072)
    im2col_k3<<<(BT * D * 3 + 255) / 256, 256>>>(hln, col1, D, BT * D * 3);
    gemm_nt_kernel<<<dim3(F / BN, BT / BM), 256>>>(col1, 3 * D, w1, 3 * D, nullptr, h1, F, 3 * D);
    // 9. gelu
    gelu_kernel<<<(BT * F + 255) / 256, 256>>>(h1, BT * F);
    // 10. conv2 via im2col + GEMM (4096 x 1024 x 12288), fused final residual
    im2col_k3<<<(BT * F * 3 + 255) / 256, 256>>>(h1, col2, F, BT * F * 3);
    gemm_nt_kernel<<<dim3(D / BN, BT / BM), 256>>>(col2, 3 * F, w2, 3 * F, x2, out, D, 3 * F);
}

// round 13
// speedup vs baseline: 1.9714x; 1.9680x over previous
#include <cuda_runtime.h>
#include <cuda_bf16.h>
#include <math.h>
#include <stdint.h>

#define Bsz 2
#define T 2048
#define D 1024
#define H 16
#define DH 64
#define F 4096
#define BT (Bsz * T)
#define TP (T + 2)   // padded rows per batch (2 leading zero rows for causal conv)

// ---------------- scratch globals -------------------------------------------
__device__ __align__(16) float g_scores[(size_t)Bsz * H * T * T]; // 512 MB
__device__ __align__(16) float g_qkv[(size_t)BT * 3 * D];
__device__ __align__(16) float g_y[(size_t)BT * D];
__device__ __align__(16) float g_x2[(size_t)BT * D];
__device__ __align__(16) __nv_bfloat16 g_qinh[(size_t)BT * D],  g_qinl[(size_t)BT * D];
__device__ __align__(16) __nv_bfloat16 g_yh[(size_t)BT * D],    g_yl[(size_t)BT * D];
__device__ __align__(16) __nv_bfloat16 g_hlnh[(size_t)Bsz * TP * D], g_hlnl[(size_t)Bsz * TP * D];
__device__ __align__(16) __nv_bfloat16 g_h1h[(size_t)Bsz * TP * F],  g_h1l[(size_t)Bsz * TP * F];
__device__ __align__(16) __nv_bfloat16 g_wqkvh[(size_t)3 * D * D], g_wqkvl[(size_t)3 * D * D];
__device__ __align__(16) __nv_bfloat16 g_woh[(size_t)D * D],    g_wol[(size_t)D * D];
__device__ __align__(16) __nv_bfloat16 g_w1h[(size_t)3 * F * D], g_w1l[(size_t)3 * F * D];
__device__ __align__(16) __nv_bfloat16 g_w2h[(size_t)3 * D * F], g_w2l[(size_t)3 * D * F];
__device__ int g_mask_is_word;

// ---------------- small helpers ---------------------------------------------
__device__ __forceinline__ float warpSum(float v) {
#pragma unroll
    for (int o = 16; o > 0; o >>= 1) v += __shfl_xor_sync(0xffffffffu, v, o);
    return v;
}
__device__ __forceinline__ float warpMax(float v) {
#pragma unroll
    for (int o = 16; o > 0; o >>= 1) v = fmaxf(v, __shfl_xor_sync(0xffffffffu, v, o));
    return v;
}
__device__ __forceinline__ void split2(float v, unsigned short& h, unsigned short& l) {
    __nv_bfloat16 hb = __float2bfloat16_rn(v);
    h = __bfloat16_as_ushort(hb);
    l = __bfloat16_as_ushort(__float2bfloat16_rn(v - __bfloat162float(hb)));
}
__device__ __forceinline__ float gelu_f(float x) {
    float u = 0.7978845608028654f * (x + 0.044715f * x * x * x);
    return 0.5f * x * (1.0f + tanhf(u));
}
__device__ __forceinline__ uint32_t smem_u32(const void* p) {
    uint32_t a;
    asm("{ .reg .u64 t; cvta.to.shared.u64 t, %1; cvt.u32.u64 %0, t; }" : "=r"(a) : "l"(p));
    return a;
}
// ---------------- sm_80-era PTX (legal at .target sm_103) --------------------
__device__ __forceinline__ void cp16(uint32_t s, const void* g) {
    asm volatile("cp.async.cg.shared.global [%0], [%1], 16;\n"
                 :: "r"(s), "l"(__cvta_generic_to_global(g)));
}
__device__ __forceinline__ void ldsm4(uint32_t* r, uint32_t addr) {
    asm volatile("ldmatrix.sync.aligned.m8n8.x4.shared.b16 {%0,%1,%2,%3}, [%4];"
                 : "=r"(r[0]), "=r"(r[1]), "=r"(r[2]), "=r"(r[3]) : "r"(addr));
}
__device__ __forceinline__ void mma_bf16(float* c, const uint32_t* a, const uint32_t* b) {
    asm volatile("mma.sync.aligned.m16n8k16.row.col.f32.bf16.bf16.f32 "
                 "{%0,%1,%2,%3}, {%4,%5,%6,%7}, {%8,%9}, {%0,%1,%2,%3};"
                 : "+f"(c[0]), "+f"(c[1]), "+f"(c[2]), "+f"(c[3])
                 : "r"(a[0]), "r"(a[1]), "r"(a[2]), "r"(a[3]), "r"(b[0]), "r"(b[1]));
}

// ---------------- mask dtype detection --------------------------------------
__global__ void detect_mask_kernel(const unsigned char* __restrict__ p) {
    g_mask_is_word = (p[3584] == 0) ? 1 : 0;
}

// ---------------- prep kernels ----------------------------------------------
__global__ void split_plain(const float* __restrict__ s, __nv_bfloat16* __restrict__ oh,
                            __nv_bfloat16* __restrict__ ol, int n) {
    int i = blockIdx.x * 256 + threadIdx.x;
    if (i >= n) return;
    unsigned short h, l;
    split2(s[i], h, l);
    oh[i] = __ushort_as_bfloat16(h);
    ol[i] = __ushort_as_bfloat16(l);
}
// (OC, IC, 3) -> per-tap (3, OC, IC) hi/lo
__global__ void split_w_k3(const float* __restrict__ w, __nv_bfloat16* __restrict__ oh,
                           __nv_bfloat16* __restrict__ ol, int OC, int IC) {
    int i = blockIdx.x * 256 + threadIdx.x;
    if (i >= OC * IC) return;
    const float* p = w + (size_t)i * 3;
#pragma unroll
    for (int k = 0; k < 3; k++) {
        unsigned short h, l;
        split2(p[k], h, l);
        size_t o = (size_t)k * OC * IC + i;
        oh[o] = __ushort_as_bfloat16(h);
        ol[o] = __ushort_as_bfloat16(l);
    }
}
__global__ void zero_pads() {
    int i = blockIdx.x * 256 + threadIdx.x;
    if (i >= 4 * F) return;
    int r = i / F, j = i - r * F;
    size_t pr = (size_t)(r >> 1) * TP + (r & 1);
    __nv_bfloat16 z = __float2bfloat16(0.f);
    g_h1h[pr * F + j] = z;
    g_h1l[pr * F + j] = z;
    if (j < D) { g_hlnh[pr * D + j] = z; g_hlnl[pr * D + j] = z; }
}

// ---------------- LayerNorm -> hi/lo bf16 ------------------------------------
__global__ void ln_split(const float* __restrict__ x, const float* __restrict__ gw,
                         const float* __restrict__ bw, const float* __restrict__ pos,
                         __nv_bfloat16* __restrict__ oh, __nv_bfloat16* __restrict__ ol,
                         int padded) {
    int row = blockIdx.x, t = row & (T - 1), tid = threadIdx.x;
    const float* xr = x + (size_t)row * D;
    float v[4], s = 0.f, sq = 0.f;
#pragma unroll
    for (int i = 0; i < 4; i++) { v[i] = xr[tid + i * 256]; s += v[i]; sq += v[i] * v[i]; }
    __shared__ float sh[16];
    s = warpSum(s); sq = warpSum(sq);
    int lane = tid & 31, wid = tid >> 5;
    if (lane == 0) { sh[wid] = s; sh[wid + 8] = sq; }
    __syncthreads();
    if (wid == 0) {
        float a = (lane < 8) ? sh[lane] : 0.f, c = (lane < 8) ? sh[lane + 8] : 0.f;
        a = warpSum(a); c = warpSum(c);
        if (lane == 0) { sh[0] = a; sh[1] = c; }
    }
    __syncthreads();
    float mu = sh[0] * (1.f / D);
    float var = sh[1] * (1.f / D) - mu * mu;
    float rstd = rsqrtf(fmaxf(var, 0.f) + 1e-5f);
    size_t orow = padded ? (size_t)(row + 2 * (row >> 11) + 2) : (size_t)row;
#pragma unroll
    for (int i = 0; i < 4; i++) {
        int d = tid + i * 256;
        float o = (v[i] - mu) * rstd * gw[d] + bw[d];
        if (pos) o += pos[(size_t)t * D + d];
        unsigned short hb, lb;
        split2(o, hb, lb);
        oh[orow * D + d] = __ushort_as_bfloat16(hb);
        ol[orow * D + d] = __ushort_as_bfloat16(lb);
    }
}

// ---------------- HMMA split-bf16 GEMM body ----------------------------------
// C[m,n] = sum_tap sum_k A[m+arow_off+tap, k] * Btap[n, k]; 128x128 tile,
// 256 threads, cp.async double-buffered, mma.sync m16n8k16 bf16, 3 terms.
#define EPI_F32 0
#define EPI_RES 1
#define EPI_GELU 2

template <int EPI, int NTAPS>
__device__ __forceinline__ void hgemm_body(
    const __nv_bfloat16* __restrict__ Ahi, const __nv_bfloat16* __restrict__ Alo,
    int lda, int arow_off,
    const __nv_bfloat16* __restrict__ Bhi, const __nv_bfloat16* __restrict__ Blo,
    int ldb, size_t btap, int Ktap,
    float* __restrict__ Cf, const float* __restrict__ R,
    __nv_bfloat16* __restrict__ Ohi, __nv_bfloat16* __restrict__ Olo,
    int ldo, int orow_off, int m0, int n0)
{
    extern __shared__ char smem[];
    constexpr int ROWB = 80;          // 32 bf16 (64B) + 16B pad: conflict-free ldmatrix
    constexpr int BUF = 128 * ROWB;   // 10240 B per operand buffer
    constexpr int STG = 4 * BUF;      // Ahi, Alo, Bhi, Blo
    const int tid = threadIdx.x, lane = tid & 31, wid = tid >> 5;
    const int wm = (wid >> 1) * 32, wn = (wid & 1) * 64;
    const uint32_t sb = smem_u32(smem);

    const int kst = Ktap / 32;
    const int nK = NTAPS * kst;

    float acc[2][8][4];
#pragma unroll
    for (int i = 0; i < 2; i++)
#pragma unroll
        for (int j = 0; j < 8; j++)
#pragma unroll
            for (int k = 0; k < 4; k++) acc[i][j][k] = 0.f;

    auto load_stage = [&](int st, int kt) {
        const int tap = (NTAPS > 1) ? (kt / kst) : 0;
        const int k0 = (kt - tap * kst) * 32;
        const uint32_t base = sb + st * STG;
        const size_t boff = btap * tap;
#pragma unroll
        for (int i = 0; i < 2; i++) {
            int q = tid * 2 + i;          // 0..511: r = row, c = 16B chunk
            int r = q >> 2, c = q & 3;
            uint32_t so = base + r * ROWB + c * 16;
            size_t ao = (size_t)(m0 + r + arow_off + tap) * lda + k0 + c * 8;
            cp16(so, Ahi + ao);
            cp16(so + BUF, Alo + ao);
            size_t bo = boff + (size_t)(n0 + r) * ldb + k0 + c * 8;
            cp16(so + 2 * BUF, Bhi + bo);
            cp16(so + 3 * BUF, Blo + bo);
        }
        asm volatile("cp.async.commit_group;\n" ::: "memory");
    };

    load_stage(0, 0);
    for (int kt = 0; kt < nK; kt++) {
        asm volatile("cp.async.wait_group 0;\n" ::: "memory");
        __syncthreads();
        if (kt + 1 < nK) load_stage((kt + 1) & 1, kt + 1);
        const uint32_t base = sb + (kt & 1) * STG;
#pragma unroll
        for (int ks = 0; ks < 2; ks++) {          // two k16 steps per 32-K stage
            uint32_t Ah[2][4], Al[2][4], Bh[8][2], Bl[8][2];
            const int j = lane >> 3, rr = lane & 7;
            const int chunk = ks * 2 + (j >> 1);
#pragma unroll
            for (int mt = 0; mt < 2; mt++) {
                uint32_t ad = base + (wm + mt * 16 + (j & 1) * 8 + rr) * ROWB + chunk * 16;
                ldsm4(Ah[mt], ad);
                ldsm4(Al[mt], ad + BUF);
            }
#pragma unroll
            for (int np = 0; np < 4; np++) {      // x4 covers 2 n8-tiles x k16
                uint32_t bd = base + 2 * BUF + (wn + np * 16 + (j & 1) * 8 + rr) * ROWB + chunk * 16;
                uint32_t t4[4];
                ldsm4(t4, bd);
                Bh[np*2][0] = t4[0]; Bh[np*2+1][0] = t4[1];
                Bh[np*2][1] = t4[2]; Bh[np*2+1][1] = t4[3];
                ldsm4(t4, bd + BUF);
                Bl[np*2][0] = t4[0]; Bl[np*2+1][0] = t4[1];
                Bl[np*2][1] = t4[2]; Bl[np*2+1][1] = t4[3];
            }
            // term-major order: 16 independent mmas between acc reuses
#pragma unroll
            for (int mt = 0; mt < 2; mt++)
#pragma unroll
                for (int nt = 0; nt < 8; nt++) mma_bf16(acc[mt][nt], Ah[mt], Bh[nt]);
#pragma unroll
            for (int mt = 0; mt < 2; mt++)
#pragma unroll
                for (int nt = 0; nt < 8; nt++) mma_bf16(acc[mt][nt], Ah[mt], Bl[nt]);
#pragma unroll
            for (int mt = 0; mt < 2; mt++)
#pragma unroll
                for (int nt = 0; nt < 8; nt++) mma_bf16(acc[mt][nt], Al[mt], Bh[nt]);
        }
    }

    // ---- epilogue ----
#pragma unroll
    for (int mt = 0; mt < 2; mt++)
#pragma unroll
        for (int nt = 0; nt < 8; nt++) {
            int r0 = m0 + wm + mt * 16 + (lane >> 2);
            int col = n0 + wn + nt * 8 + (lane & 3) * 2;
            float* a4 = acc[mt][nt];
#pragma unroll
            for (int hh = 0; hh < 2; hh++) {
                int row = r0 + hh * 8;
                float v0 = a4[hh * 2 + 0], v1 = a4[hh * 2 + 1];
                if (EPI == EPI_GELU) {
                    v0 = gelu_f(v0); v1 = gelu_f(v1);
                    unsigned short h0, l0, h1, l1;
                    split2(v0, h0, l0); split2(v1, h1, l1);
                    size_t oo = (size_t)(row + orow_off) * ldo + col;
                    *(uint32_t*)(Ohi + oo) = (uint32_t)h0 | ((uint32_t)h1 << 16);
                    *(uint32_t*)(Olo + oo) = (uint32_t)l0 | ((uint32_t)l1 << 16);
                } else {
                    size_t oo = (size_t)row * ldo + col;
                    if (EPI == EPI_RES) {
                        float2 rr = *(const float2*)(R + oo);
                        v0 += rr.x; v1 += rr.y;
                    }
                    float2 v = make_float2(v0, v1);
                    *(float2*)(Cf + oo) = v;
                }
            }
        }
}

#define HG_SMEM (2 * 4 * 128 * 80)   // 81920 B

__global__ __launch_bounds__(256, 1) void k_qkv() {
    hgemm_body<EPI_F32, 1>(g_qinh, g_qinl, D, 0, g_wqkvh, g_wqkvl, D, 0, D,
                           g_qkv, nullptr, nullptr, nullptr, 3 * D, 0,
                           blockIdx.y * 128, blockIdx.x * 128);
}
__global__ __launch_bounds__(256, 1) void k_oproj(const float* __restrict__ x) {
    hgemm_body<EPI_RES, 1>(g_yh, g_yl, D, 0, g_woh, g_wol, D, 0, D,
                           g_x2, x, nullptr, nullptr, D, 0,
                           blockIdx.y * 128, blockIdx.x * 128);
}
__global__ __launch_bounds__(256, 1) void k_conv1() {
    int m0 = blockIdx.y * 128, b = m0 >> 11;
    hgemm_body<EPI_GELU, 3>(g_hlnh, g_hlnl, D, 2 * b, g_w1h, g_w1l, D, (size_t)F * D, D,
                            nullptr, nullptr, g_h1h, g_h1l, F, 2 * b + 2,
                            m0, blockIdx.x * 128);
}
__global__ __launch_bounds__(256, 1) void k_conv2(float* __restrict__ out) {
    int m0 = blockIdx.y * 128, b = m0 >> 11;
    hgemm_body<EPI_RES, 3>(g_h1h, g_h1l, F, 2 * b, g_w2h, g_w2l, F, (size_t)D * F, F,
                           out, g_x2, nullptr, nullptr, D, 0,
                           m0, blockIdx.x * 128);
}

// ---------------- fp32 attention path (unchanged, known-good) ----------------
#define BM 128
#define BN 128
#define BK 8
__device__ __forceinline__ void gemm_nt_body(
    const float* __restrict__ A, int lda, const float* __restrict__ B, int ldb,
    float* __restrict__ C, int ldc, int K, int m0, int n0)
{
    __shared__ float As[BK][BM + 4];
    __shared__ float Bs[BK][BN + 4];
    int tid = threadIdx.x;
    int tx = tid & 15, ty = tid >> 4;
    int lrow = tid >> 1, lcol = (tid & 1) * 4;
    const float* Ap = A + (size_t)(m0 + lrow) * lda + lcol;
    const float* Bp = B + (size_t)(n0 + lrow) * ldb + lcol;
    float acc[8][8];
#pragma unroll
    for (int i = 0; i < 8; i++)
#pragma unroll
        for (int j = 0; j < 8; j++) acc[i][j] = 0.f;
    for (int k0 = 0; k0 < K; k0 += BK) {
        float4 av = *(const float4*)(Ap + k0);
        float4 bv = *(const float4*)(Bp + k0);
        As[lcol + 0][lrow] = av.x; As[lcol + 1][lrow] = av.y;
        As[lcol + 2][lrow] = av.z; As[lcol + 3][lrow] = av.w;
        Bs[lcol + 0][lrow] = bv.x; Bs[lcol + 1][lrow] = bv.y;
        Bs[lcol + 2][lrow] = bv.z; Bs[lcol + 3][lrow] = bv.w;
        __syncthreads();
#pragma unroll
        for (int kk = 0; kk < BK; kk++) {
            float a[8], b[8];
#pragma unroll
            for (int i = 0; i < 8; i++) a[i] = As[kk][ty * 8 + i];
#pragma unroll
            for (int j = 0; j < 8; j++) b[j] = Bs[kk][tx * 8 + j];
#pragma unroll
            for (int i = 0; i < 8; i++)
#pragma unroll
                for (int j = 0; j < 8; j++) acc[i][j] = fmaf(a[i], b[j], acc[i][j]);
        }
        __syncthreads();
    }
#pragma unroll
    for (int i = 0; i < 8; i++) {
        size_t cr = (size_t)(m0 + ty * 8 + i) * ldc + n0 + tx * 8;
#pragma unroll
        for (int j = 0; j < 8; j++) C[cr + j] = acc[i][j];
    }
}
__global__ void scores_kernel() {
    int z = blockIdx.z, b = z >> 4, h = z & 15;
    int m0 = blockIdx.y * BM, n0 = blockIdx.x * BN;
    if (n0 > m0) return;
    const float* q = g_qkv + (size_t)b * T * 3 * D + h * DH;
    gemm_nt_body(q, 3 * D, q + D, 3 * D, g_scores + (size_t)z * T * T, T, DH, m0, n0);
}
__global__ void softmax_kernel(const void* __restrict__ maskp) {
    int row = blockIdx.x, t = row & (T - 1), b = row >> 15;
    float* sr = g_scores + (size_t)row * T;
    int tid = threadIdx.x;
    int slimit = ((t >> 7) + 1) << 7;
    const float scale = 0.125f;
    bool word = (g_mask_is_word != 0);
    bool padded = word ? (((const int*)maskp)[b * T + t] != 0)
                       : (((const unsigned char*)maskp)[b * T + t] != 0);
    if (padded) {
        for (int s = tid; s < slimit; s += 256) sr[s] = 0.f;
        return;
    }
    float v[8], m = -1e30f;
#pragma unroll
    for (int i = 0; i < 8; i++) {
        int s = tid + i * 256;
        float val = -1e30f;
        if (s < slimit) val = (s > t) ? -1e9f : sr[s] * scale;
        v[i] = val;
        m = fmaxf(m, val);
    }
    __shared__ float sh[8];
    __shared__ float bc;
    m = warpMax(m);
    int lane = tid & 31, wid = tid >> 5;
    if (lane == 0) sh[wid] = m;
    __syncthreads();
    if (wid == 0) {
        float a = (lane < 8) ? sh[lane] : -1e30f;
        a = warpMax(a);
        if (lane == 0) bc = a;
    }
    __syncthreads();
    float M = bc, sum = 0.f;
#pragma unroll
    for (int i = 0; i < 8; i++) { float e = __expf(v[i] - M); v[i] = e; sum += e; }
    __syncthreads();
    sum = warpSum(sum);
    if (lane == 0) sh[wid] = sum;
    __syncthreads();
    if (wid == 0) {
        float a = (lane < 8) ? sh[lane] : 0.f;
        a = warpSum(a);
        if (lane == 0) bc = a;
    }
    __syncthreads();
    float inv = 1.f / bc;
#pragma unroll
    for (int i = 0; i < 8; i++) {
        int s = tid + i * 256;
        if (s < slimit) sr[s] = v[i] * inv;
    }
}
#define PVM 128
#define PVK 16
__global__ void pv_kernel() {
    int z = blockIdx.z, b = z >> 4, h = z & 15;
    const float* P = g_scores + (size_t)z * T * T;
    const float* V = g_qkv + (size_t)b * T * 3 * D + 2 * D + h * DH;
    float* C = g_y + (size_t)b * T * D + h * DH;
    int m0 = blockIdx.y * PVM;
    __shared__ float Ps[PVK][PVM + 4];
    __shared__ float Vs[PVK][64 + 4];
    int tid = threadIdx.x;
    int tx = tid & 15, ty = tid >> 4;
    int prow = tid >> 1, pc = (tid & 1) * 8;
    int vk = tid >> 4, vn = (tid & 15) * 4;
    float acc[8][4];
#pragma unroll
    for (int i = 0; i < 8; i++)
#pragma unroll
        for (int j = 0; j < 4; j++) acc[i][j] = 0.f;
    int Klim = m0 + PVM;
    for (int k0 = 0; k0 < Klim; k0 += PVK) {
        const float* pr = P + (size_t)(m0 + prow) * T + k0 + pc;
        float4 p0 = *(const float4*)pr;
        float4 p1 = *(const float4*)(pr + 4);
        Ps[pc + 0][prow] = p0.x; Ps[pc + 1][prow] = p0.y;
        Ps[pc + 2][prow] = p0.z; Ps[pc + 3][prow] = p0.w;
        Ps[pc + 4][prow] = p1.x; Ps[pc + 5][prow] = p1.y;
        Ps[pc + 6][prow] = p1.z; Ps[pc + 7][prow] = p1.w;
        float4 vv = *(const float4*)(V + (size_t)(k0 + vk) * (3 * D) + vn);
        Vs[vk][vn + 0] = vv.x; Vs[vk][vn + 1] = vv.y;
        Vs[vk][vn + 2] = vv.z; Vs[vk][vn + 3] = vv.w;
        __syncthreads();
#pragma unroll
        for (int kk = 0; kk < PVK; kk++) {
            float a[8], bb[4];
#pragma unroll
            for (int i = 0; i < 8; i++) a[i] = Ps[kk][ty * 8 + i];
#pragma unroll
            for (int j = 0; j < 4; j++) bb[j] = Vs[kk][tx * 4 + j];
#pragma unroll
            for (int i = 0; i < 8; i++)
#pragma unroll
                for (int j = 0; j < 4; j++) acc[i][j] = fmaf(a[i], bb[j], acc[i][j]);
        }
        __syncthreads();
    }
#pragma unroll
    for (int i = 0; i < 8; i++) {
        size_t cr = (size_t)(m0 + ty * 8 + i) * D + tx * 4;
#pragma unroll
        for (int j = 0; j < 4; j++) C[cr + j] = acc[i][j];
    }
}

// ---------------- launch ----------------------------------------------------
extern "C" void kernel_launch(void* const* d_in, const int* in_sizes, int n_in,
                              void* d_out, int out_size) {
    const float* x     = (const float*)d_in[0];
    const void*  mask  = d_in[1];
    const float* pos   = (const float*)d_in[2];
    const float* w_qkv = (const float*)d_in[3];
    const float* w_o   = (const float*)d_in[4];
    const float* ln1g  = (const float*)d_in[5];
    const float* ln1b  = (const float*)d_in[6];
    const float* ln2g  = (const float*)d_in[7];
    const float* ln2b  = (const float*)d_in[8];
    const float* w1    = (const float*)d_in[9];
    const float* w2    = (const float*)d_in[10];
    float* out = (float*)d_out;

    cudaFuncSetAttribute(k_qkv,   cudaFuncAttributeMaxDynamicSharedMemorySize, HG_SMEM);
    cudaFuncSetAttribute(k_oproj, cudaFuncAttributeMaxDynamicSharedMemorySize, HG_SMEM);
    cudaFuncSetAttribute(k_conv1, cudaFuncAttributeMaxDynamicSharedMemorySize, HG_SMEM);
    cudaFuncSetAttribute(k_conv2, cudaFuncAttributeMaxDynamicSharedMemorySize, HG_SMEM);

    float *x2_d, *y_d;
    cudaGetSymbolAddress((void**)&x2_d, g_x2);
    cudaGetSymbolAddress((void**)&y_d,  g_y);
    __nv_bfloat16 *wqh, *wql, *woh, *wol, *w1h, *w1l, *w2h, *w2l, *qih, *qil, *yh, *yl, *hlh, *hll;
    cudaGetSymbolAddress((void**)&wqh, g_wqkvh);  cudaGetSymbolAddress((void**)&wql, g_wqkvl);
    cudaGetSymbolAddress((void**)&woh, g_woh);    cudaGetSymbolAddress((void**)&wol, g_wol);
    cudaGetSymbolAddress((void**)&w1h, g_w1h);    cudaGetSymbolAddress((void**)&w1l, g_w1l);
    cudaGetSymbolAddress((void**)&w2h, g_w2h);    cudaGetSymbolAddress((void**)&w2l, g_w2l);
    cudaGetSymbolAddress((void**)&qih, g_qinh);   cudaGetSymbolAddress((void**)&qil, g_qinl);
    cudaGetSymbolAddress((void**)&yh,  g_yh);     cudaGetSymbolAddress((void**)&yl,  g_yl);
    cudaGetSymbolAddress((void**)&hlh, g_hlnh);   cudaGetSymbolAddress((void**)&hll, g_hlnl);

    detect_mask_kernel<<<1, 1>>>((const unsigned char*)mask);
    // weight prep (every launch; deterministic)
    split_plain<<<(3 * D * D + 255) / 256, 256>>>(w_qkv, wqh, wql, 3 * D * D);
    split_plain<<<(D * D + 255) / 256, 256>>>(w_o, woh, wol, D * D);
    split_w_k3<<<(F * D + 255) / 256, 256>>>(w1, w1h, w1l, F, D);
    split_w_k3<<<(D * F + 255) / 256, 256>>>(w2, w2h, w2l, D, F);
    zero_pads<<<(4 * F + 255) / 256, 256>>>();

    // attention
    ln_split<<<BT, 256>>>(x, ln1g, ln1b, pos, qih, qil, 0);
    k_qkv<<<dim3(3 * D / 128, BT / 128), 256, HG_SMEM>>>();
    scores_kernel<<<dim3(T / 128, T / 128, Bsz * H), 256>>>();
    softmax_kernel<<<Bsz * H * T, 256>>>(mask);
    pv_kernel<<<dim3(1, T / PVM, Bsz * H), 256>>>();
    split_plain<<<(BT * D + 255) / 256, 256>>>(y_d, yh, yl, BT * D);
    k_oproj<<<dim3(D / 128, BT / 128), 256, HG_SMEM>>>(x);

    // conv block
    ln_split<<<BT, 256>>>(x2_d, ln2g, ln2b, nullptr, hlh, hll, 1);
    k_conv1<<<dim3(F / 128, BT / 128), 256, HG_SMEM>>>();
    k_conv2<<<dim3(D / 128, BT / 128), 256, HG_SMEM>>>(out);
}

// round 14
// speedup vs baseline: 2.1302x; 1.0806x over previous
#include <cuda_runtime.h>
#include <cuda_bf16.h>
#include <math.h>
#include <stdint.h>

#define Bsz 2
#define T 2048
#define D 1024
#define H 16
#define DH 64
#define F 4096
#define BT (Bsz * T)
#define TP (T + 2)   // padded rows per batch (2 leading zero rows for causal conv)

// ---------------- scratch globals -------------------------------------------
__device__ __align__(16) float g_scores[(size_t)Bsz * H * T * T]; // 512 MB (f32 logits)
__device__ __align__(16) float g_x2[(size_t)BT * D];
__device__ __align__(16) __nv_bfloat16 g_ph[(size_t)Bsz * H * T * T];  // 256 MB probs hi
__device__ __align__(16) __nv_bfloat16 g_pl[(size_t)Bsz * H * T * T];  // 256 MB probs lo
__device__ __align__(16) __nv_bfloat16 g_vth[(size_t)Bsz * H * DH * T], g_vtl[(size_t)Bsz * H * DH * T];
__device__ __align__(16) __nv_bfloat16 g_qinh[(size_t)BT * D],  g_qinl[(size_t)BT * D];
__device__ __align__(16) __nv_bfloat16 g_qkvh[(size_t)BT * 3 * D], g_qkvl[(size_t)BT * 3 * D];
__device__ __align__(16) __nv_bfloat16 g_yh[(size_t)BT * D],    g_yl[(size_t)BT * D];
__device__ __align__(16) __nv_bfloat16 g_hlnh[(size_t)Bsz * TP * D], g_hlnl[(size_t)Bsz * TP * D];
__device__ __align__(16) __nv_bfloat16 g_h1h[(size_t)Bsz * TP * F],  g_h1l[(size_t)Bsz * TP * F];
__device__ __align__(16) __nv_bfloat16 g_wqkvh[(size_t)3 * D * D], g_wqkvl[(size_t)3 * D * D];
__device__ __align__(16) __nv_bfloat16 g_woh[(size_t)D * D],    g_wol[(size_t)D * D];
__device__ __align__(16) __nv_bfloat16 g_w1h[(size_t)3 * F * D], g_w1l[(size_t)3 * F * D];
__device__ __align__(16) __nv_bfloat16 g_w2h[(size_t)3 * D * F], g_w2l[(size_t)3 * D * F];
__device__ int g_mask_is_word;

// ---------------- small helpers ---------------------------------------------
__device__ __forceinline__ float warpSum(float v) {
#pragma unroll
    for (int o = 16; o > 0; o >>= 1) v += __shfl_xor_sync(0xffffffffu, v, o);
    return v;
}
__device__ __forceinline__ float warpMax(float v) {
#pragma unroll
    for (int o = 16; o > 0; o >>= 1) v = fmaxf(v, __shfl_xor_sync(0xffffffffu, v, o));
    return v;
}
__device__ __forceinline__ void split2(float v, unsigned short& h, unsigned short& l) {
    __nv_bfloat16 hb = __float2bfloat16_rn(v);
    h = __bfloat16_as_ushort(hb);
    l = __bfloat16_as_ushort(__float2bfloat16_rn(v - __bfloat162float(hb)));
}
__device__ __forceinline__ float gelu_f(float x) {
    float u = 0.7978845608028654f * (x + 0.044715f * x * x * x);
    return 0.5f * x * (1.0f + tanhf(u));
}
__device__ __forceinline__ uint32_t smem_u32(const void* p) {
    uint32_t a;
    asm("{ .reg .u64 t; cvta.to.shared.u64 t, %1; cvt.u32.u64 %0, t; }" : "=r"(a) : "l"(p));
    return a;
}
// ---------------- sm_80-era PTX (legal at .target sm_103) --------------------
__device__ __forceinline__ void cp16(uint32_t s, const void* g) {
    asm volatile("cp.async.cg.shared.global [%0], [%1], 16;\n"
                 :: "r"(s), "l"(__cvta_generic_to_global(g)));
}
__device__ __forceinline__ void ldsm4(uint32_t* r, uint32_t addr) {
    asm volatile("ldmatrix.sync.aligned.m8n8.x4.shared.b16 {%0,%1,%2,%3}, [%4];"
                 : "=r"(r[0]), "=r"(r[1]), "=r"(r[2]), "=r"(r[3]) : "r"(addr));
}
__device__ __forceinline__ void mma_bf16(float* c, const uint32_t* a, const uint32_t* b) {
    asm volatile("mma.sync.aligned.m16n8k16.row.col.f32.bf16.bf16.f32 "
                 "{%0,%1,%2,%3}, {%4,%5,%6,%7}, {%8,%9}, {%0,%1,%2,%3};"
                 : "+f"(c[0]), "+f"(c[1]), "+f"(c[2]), "+f"(c[3])
                 : "r"(a[0]), "r"(a[1]), "r"(a[2]), "r"(a[3]), "r"(b[0]), "r"(b[1]));
}

// ---------------- mask dtype detection --------------------------------------
__global__ void detect_mask_kernel(const unsigned char* __restrict__ p) {
    g_mask_is_word = (p[3584] == 0) ? 1 : 0;
}

// ---------------- prep kernels ----------------------------------------------
__global__ void split_plain(const float* __restrict__ s, __nv_bfloat16* __restrict__ oh,
                            __nv_bfloat16* __restrict__ ol, int n) {
    int i = blockIdx.x * 256 + threadIdx.x;
    if (i >= n) return;
    unsigned short h, l;
    split2(s[i], h, l);
    oh[i] = __ushort_as_bfloat16(h);
    ol[i] = __ushort_as_bfloat16(l);
}
// (OC, IC, 3) -> per-tap (3, OC, IC) hi/lo
__global__ void split_w_k3(const float* __restrict__ w, __nv_bfloat16* __restrict__ oh,
                           __nv_bfloat16* __restrict__ ol, int OC, int IC) {
    int i = blockIdx.x * 256 + threadIdx.x;
    if (i >= OC * IC) return;
    const float* p = w + (size_t)i * 3;
#pragma unroll
    for (int k = 0; k < 3; k++) {
        unsigned short h, l;
        split2(p[k], h, l);
        size_t o = (size_t)k * OC * IC + i;
        oh[o] = __ushort_as_bfloat16(h);
        ol[o] = __ushort_as_bfloat16(l);
    }
}
__global__ void zero_pads() {
    int i = blockIdx.x * 256 + threadIdx.x;
    if (i >= 4 * F) return;
    int r = i / F, j = i - r * F;
    size_t pr = (size_t)(r >> 1) * TP + (r & 1);
    __nv_bfloat16 z = __float2bfloat16(0.f);
    g_h1h[pr * F + j] = z;
    g_h1l[pr * F + j] = z;
    if (j < D) { g_hlnh[pr * D + j] = z; g_hlnl[pr * D + j] = z; }
}

// ---------------- LayerNorm -> hi/lo bf16 ------------------------------------
__global__ void ln_split(const float* __restrict__ x, const float* __restrict__ gw,
                         const float* __restrict__ bw, const float* __restrict__ pos,
                         __nv_bfloat16* __restrict__ oh, __nv_bfloat16* __restrict__ ol,
                         int padded) {
    int row = blockIdx.x, t = row & (T - 1), tid = threadIdx.x;
    const float* xr = x + (size_t)row * D;
    float v[4], s = 0.f, sq = 0.f;
#pragma unroll
    for (int i = 0; i < 4; i++) { v[i] = xr[tid + i * 256]; s += v[i]; sq += v[i] * v[i]; }
    __shared__ float sh[16];
    s = warpSum(s); sq = warpSum(sq);
    int lane = tid & 31, wid = tid >> 5;
    if (lane == 0) { sh[wid] = s; sh[wid + 8] = sq; }
    __syncthreads();
    if (wid == 0) {
        float a = (lane < 8) ? sh[lane] : 0.f, c = (lane < 8) ? sh[lane + 8] : 0.f;
        a = warpSum(a); c = warpSum(c);
        if (lane == 0) { sh[0] = a; sh[1] = c; }
    }
    __syncthreads();
    float mu = sh[0] * (1.f / D);
    float var = sh[1] * (1.f / D) - mu * mu;
    float rstd = rsqrtf(fmaxf(var, 0.f) + 1e-5f);
    size_t orow = padded ? (size_t)(row + 2 * (row >> 11) + 2) : (size_t)row;
#pragma unroll
    for (int i = 0; i < 4; i++) {
        int d = tid + i * 256;
        float o = (v[i] - mu) * rstd * gw[d] + bw[d];
        if (pos) o += pos[(size_t)t * D + d];
        unsigned short hb, lb;
        split2(o, hb, lb);
        oh[orow * D + d] = __ushort_as_bfloat16(hb);
        ol[orow * D + d] = __ushort_as_bfloat16(lb);
    }
}

// ---------------- V transpose: [s, dh] -> [dh, s] per (b,h), hi+lo -----------
__global__ void transpose_v() {
    __shared__ __nv_bfloat16 th[32][33], tl[32][33];
    int z = blockIdx.z, b = z >> 4, h = z & 15;
    int tx = threadIdx.x, ty = threadIdx.y;
    int s_in = blockIdx.x * 32 + ty;
    int d_in = blockIdx.y * 32 + tx;
    size_t in = (size_t)b * T * 3 * D + (size_t)s_in * 3 * D + 2 * D + h * DH + d_in;
    th[ty][tx] = g_qkvh[in];
    tl[ty][tx] = g_qkvl[in];
    __syncthreads();
    int s_out = blockIdx.x * 32 + tx;
    int d_out = blockIdx.y * 32 + ty;
    size_t out = (size_t)z * DH * T + (size_t)d_out * T + s_out;
    g_vth[out] = th[tx][ty];
    g_vtl[out] = tl[tx][ty];
}

// ---------------- HMMA split-bf16 GEMM body ----------------------------------
// C[m,n] = sum_tap sum_k A[m+arow_off+tap, k] * Btap[n, k]
// 128 x (NT*16) tile, 256 threads, cp.async double-buffered, 3-term split.
#define EPI_F32 0
#define EPI_RES 1
#define EPI_GELU 2
#define EPI_SPLIT 3

template <int EPI, int NTAPS, int NT>
__device__ __forceinline__ void hgemm_body(
    const __nv_bfloat16* __restrict__ Ahi, const __nv_bfloat16* __restrict__ Alo,
    int lda, int arow_off,
    const __nv_bfloat16* __restrict__ Bhi, const __nv_bfloat16* __restrict__ Blo,
    int ldb, size_t btap, int Ktap,
    float* __restrict__ Cf, const float* __restrict__ R,
    __nv_bfloat16* __restrict__ Ohi, __nv_bfloat16* __restrict__ Olo,
    int ldo, int orow_off, int m0, int n0)
{
    extern __shared__ char smem[];
    constexpr int BN = NT * 16;       // 128 (NT=8) or 64 (NT=4)
    constexpr int ROWB = 80;          // 64B data + 16B pad: conflict-free ldmatrix
    constexpr int ABUF = 128 * ROWB;
    constexpr int BBUF = BN * ROWB;
    constexpr int STG = 2 * ABUF + 2 * BBUF;
    const int tid = threadIdx.x, lane = tid & 31, wid = tid >> 5;
    const int wm = (wid >> 1) * 32, wn = (wid & 1) * (NT * 8);
    const uint32_t sb = smem_u32(smem);

    const int kst = Ktap / 32;
    const int nK = NTAPS * kst;

    float acc[2][NT][4];
#pragma unroll
    for (int i = 0; i < 2; i++)
#pragma unroll
        for (int j = 0; j < NT; j++)
#pragma unroll
            for (int k = 0; k < 4; k++) acc[i][j][k] = 0.f;

    auto load_stage = [&](int st, int kt) {
        const int tap = (NTAPS > 1) ? (kt / kst) : 0;
        const int k0 = (kt - tap * kst) * 32;
        const uint32_t base = sb + st * STG;
        const size_t boff = btap * tap;
#pragma unroll
        for (int i = 0; i < 2; i++) {
            int q = tid * 2 + i;          // r = row, c = 16B chunk
            int r = q >> 2, c = q & 3;
            uint32_t so = base + r * ROWB + c * 16;
            size_t ao = (size_t)(m0 + r + arow_off + tap) * lda + k0 + c * 8;
            cp16(so, Ahi + ao);
            cp16(so + ABUF, Alo + ao);
            if (r < BN) {
                size_t bo = boff + (size_t)(n0 + r) * ldb + k0 + c * 8;
                uint32_t sob = base + 2 * ABUF + r * ROWB + c * 16;
                cp16(sob, Bhi + bo);
                cp16(sob + BBUF, Blo + bo);
            }
        }
        asm volatile("cp.async.commit_group;\n" ::: "memory");
    };

    load_stage(0, 0);
    for (int kt = 0; kt < nK; kt++) {
        asm volatile("cp.async.wait_group 0;\n" ::: "memory");
        __syncthreads();
        if (kt + 1 < nK) load_stage((kt + 1) & 1, kt + 1);
        const uint32_t base = sb + (kt & 1) * STG;
#pragma unroll
        for (int ks = 0; ks < 2; ks++) {          // two k16 steps per 32-K stage
            uint32_t Ah[2][4], Al[2][4], Bh[8][2], Bl[8][2];
            const int j = lane >> 3, rr = lane & 7;
            const int chunk = ks * 2 + (j >> 1);
#pragma unroll
            for (int mt = 0; mt < 2; mt++) {
                uint32_t ad = base + (wm + mt * 16 + (j & 1) * 8 + rr) * ROWB + chunk * 16;
                ldsm4(Ah[mt], ad);
                ldsm4(Al[mt], ad + ABUF);
            }
#pragma unroll
            for (int np = 0; np < NT / 2; np++) { // each x4 covers 2 n8-tiles
                uint32_t bd = base + 2 * ABUF + (wn + np * 16 + (j & 1) * 8 + rr) * ROWB + chunk * 16;
                uint32_t t4[4];
                ldsm4(t4, bd);
                Bh[np*2][0] = t4[0]; Bh[np*2+1][0] = t4[1];
                Bh[np*2][1] = t4[2]; Bh[np*2+1][1] = t4[3];
                ldsm4(t4, bd + BBUF);
                Bl[np*2][0] = t4[0]; Bl[np*2+1][0] = t4[1];
                Bl[np*2][1] = t4[2]; Bl[np*2+1][1] = t4[3];
            }
#pragma unroll
            for (int mt = 0; mt < 2; mt++)
#pragma unroll
                for (int nt = 0; nt < NT; nt++) mma_bf16(acc[mt][nt], Ah[mt], Bh[nt]);
#pragma unroll
            for (int mt = 0; mt < 2; mt++)
#pragma unroll
                for (int nt = 0; nt < NT; nt++) mma_bf16(acc[mt][nt], Ah[mt], Bl[nt]);
#pragma unroll
            for (int mt = 0; mt < 2; mt++)
#pragma unroll
                for (int nt = 0; nt < NT; nt++) mma_bf16(acc[mt][nt], Al[mt], Bh[nt]);
        }
    }

    // ---- epilogue ----
#pragma unroll
    for (int mt = 0; mt < 2; mt++)
#pragma unroll
        for (int nt = 0; nt < NT; nt++) {
            int r0 = m0 + wm + mt * 16 + (lane >> 2);
            int col = n0 + wn + nt * 8 + (lane & 3) * 2;
            float* a4 = acc[mt][nt];
#pragma unroll
            for (int hh = 0; hh < 2; hh++) {
                int row = r0 + hh * 8;
                float v0 = a4[hh * 2 + 0], v1 = a4[hh * 2 + 1];
                if (EPI == EPI_GELU || EPI == EPI_SPLIT) {
                    if (EPI == EPI_GELU) { v0 = gelu_f(v0); v1 = gelu_f(v1); }
                    unsigned short h0, l0, h1, l1;
                    split2(v0, h0, l0); split2(v1, h1, l1);
                    size_t oo = (size_t)(row + orow_off) * ldo + col;
                    *(uint32_t*)(Ohi + oo) = (uint32_t)h0 | ((uint32_t)h1 << 16);
                    *(uint32_t*)(Olo + oo) = (uint32_t)l0 | ((uint32_t)l1 << 16);
                } else {
                    size_t oo = (size_t)row * ldo + col;
                    if (EPI == EPI_RES) {
                        float2 rr = *(const float2*)(R + oo);
                        v0 += rr.x; v1 += rr.y;
                    }
                    *(float2*)(Cf + oo) = make_float2(v0, v1);
                }
            }
        }
}

#define HG_SMEM (2 * 4 * 128 * 80)               // NT=8: 81920 B
#define PV_SMEM (2 * (2 * 128 * 80 + 2 * 64 * 80)) // NT=4: 61440 B

__global__ __launch_bounds__(256, 1) void k_qkv() {
    hgemm_body<EPI_SPLIT, 1, 8>(g_qinh, g_qinl, D, 0, g_wqkvh, g_wqkvl, D, 0, D,
                                nullptr, nullptr, g_qkvh, g_qkvl, 3 * D, 0,
                                blockIdx.y * 128, blockIdx.x * 128);
}
__global__ __launch_bounds__(256, 1) void k_scores() {
    int m0 = blockIdx.y * 128, n0 = blockIdx.x * 128;
    if (n0 > m0) return;   // fully above causal diagonal
    int z = blockIdx.z, b = z >> 4, h = z & 15;
    const __nv_bfloat16* qh = g_qkvh + (size_t)b * T * 3 * D + h * DH;
    const __nv_bfloat16* ql = g_qkvl + (size_t)b * T * 3 * D + h * DH;
    hgemm_body<EPI_F32, 1, 8>(qh, ql, 3 * D, 0, qh + D, ql + D, 3 * D, 0, DH,
                              g_scores + (size_t)z * T * T, nullptr,
                              nullptr, nullptr, T, 0, m0, n0);
}
__global__ __launch_bounds__(256, 1) void k_pv() {
    int m0 = blockIdx.y * 128;
    int z = blockIdx.z, b = z >> 4, h = z & 15;
    hgemm_body<EPI_SPLIT, 1, 4>(g_ph + (size_t)z * T * T, g_pl + (size_t)z * T * T, T, 0,
                                g_vth + (size_t)z * DH * T, g_vtl + (size_t)z * DH * T, T, 0,
                                m0 + 128,   // causal K limit
                                nullptr, nullptr,
                                g_yh + (size_t)b * T * D + h * DH,
                                g_yl + (size_t)b * T * D + h * DH, D, 0, m0, 0);
}
__global__ __launch_bounds__(256, 1) void k_oproj(const float* __restrict__ x) {
    hgemm_body<EPI_RES, 1, 8>(g_yh, g_yl, D, 0, g_woh, g_wol, D, 0, D,
                              g_x2, x, nullptr, nullptr, D, 0,
                              blockIdx.y * 128, blockIdx.x * 128);
}
__global__ __launch_bounds__(256, 1) void k_conv1() {
    int m0 = blockIdx.y * 128, b = m0 >> 11;
    hgemm_body<EPI_GELU, 3, 8>(g_hlnh, g_hlnl, D, 2 * b, g_w1h, g_w1l, D, (size_t)F * D, D,
                               nullptr, nullptr, g_h1h, g_h1l, F, 2 * b + 2,
                               m0, blockIdx.x * 128);
}
__global__ __launch_bounds__(256, 1) void k_conv2(float* __restrict__ out) {
    int m0 = blockIdx.y * 128, b = m0 >> 11;
    hgemm_body<EPI_RES, 3, 8>(g_h1h, g_h1l, F, 2 * b, g_w2h, g_w2l, F, (size_t)D * F, F,
                              out, g_x2, nullptr, nullptr, D, 0,
                              m0, blockIdx.x * 128);
}

// ---------------- softmax: f32 logits -> hi/lo bf16 probs --------------------
// pad_mask broadcasts over QUERY axis; padded query row -> zero prob row.
// Writes s < slimit = (t/128+1)*128 which exactly covers PV's read window.
__global__ void softmax_kernel(const void* __restrict__ maskp) {
    int row = blockIdx.x, t = row & (T - 1), b = row >> 15;
    const float* sr = g_scores + (size_t)row * T;
    __nv_bfloat16* ph = g_ph + (size_t)row * T;
    __nv_bfloat16* pl = g_pl + (size_t)row * T;
    int tid = threadIdx.x;
    int slimit = ((t >> 7) + 1) << 7;
    const float scale = 0.125f;
    bool word = (g_mask_is_word != 0);
    bool padded = word ? (((const int*)maskp)[b * T + t] != 0)
                       : (((const unsigned char*)maskp)[b * T + t] != 0);
    if (padded) {
        __nv_bfloat16 z = __float2bfloat16(0.f);
        for (int s = tid; s < slimit; s += 256) { ph[s] = z; pl[s] = z; }
        return;
    }
    float v[8], m = -1e30f;
#pragma unroll
    for (int i = 0; i < 8; i++) {
        int s = tid + i * 256;
        float val = -1e30f;
        if (s < slimit) val = (s > t) ? -1e9f : sr[s] * scale;
        v[i] = val;
        m = fmaxf(m, val);
    }
    __shared__ float sh[8];
    __shared__ float bc;
    m = warpMax(m);
    int lane = tid & 31, wid = tid >> 5;
    if (lane == 0) sh[wid] = m;
    __syncthreads();
    if (wid == 0) {
        float a = (lane < 8) ? sh[lane] : -1e30f;
        a = warpMax(a);
        if (lane == 0) bc = a;
    }
    __syncthreads();
    float M = bc, sum = 0.f;
#pragma unroll
    for (int i = 0; i < 8; i++) { float e = __expf(v[i] - M); v[i] = e; sum += e; }
    __syncthreads();
    sum = warpSum(sum);
    if (lane == 0) sh[wid] = sum;
    __syncthreads();
    if (wid == 0) {
        float a = (lane < 8) ? sh[lane] : 0.f;
        a = warpSum(a);
        if (lane == 0) bc = a;
    }
    __syncthreads();
    float inv = 1.f / bc;
#pragma unroll
    for (int i = 0; i < 8; i++) {
        int s = tid + i * 256;
        if (s < slimit) {
            unsigned short hb, lb;
            split2(v[i] * inv, hb, lb);
            ph[s] = __ushort_as_bfloat16(hb);
            pl[s] = __ushort_as_bfloat16(lb);
        }
    }
}

// ---------------- launch ----------------------------------------------------
extern "C" void kernel_launch(void* const* d_in, const int* in_sizes, int n_in,
                              void* d_out, int out_size) {
    const float* x     = (const float*)d_in[0];
    const void*  mask  = d_in[1];
    const float* pos   = (const float*)d_in[2];
    const float* w_qkv = (const float*)d_in[3];
    const float* w_o   = (const float*)d_in[4];
    const float* ln1g  = (const float*)d_in[5];
    const float* ln1b  = (const float*)d_in[6];
    const float* ln2g  = (const float*)d_in[7];
    const float* ln2b  = (const float*)d_in[8];
    const float* w1    = (const float*)d_in[9];
    const float* w2    = (const float*)d_in[10];
    float* out = (float*)d_out;

    cudaFuncSetAttribute(k_qkv,    cudaFuncAttributeMaxDynamicSharedMemorySize, HG_SMEM);
    cudaFuncSetAttribute(k_scores, cudaFuncAttributeMaxDynamicSharedMemorySize, HG_SMEM);
    cudaFuncSetAttribute(k_pv,     cudaFuncAttributeMaxDynamicSharedMemorySize, PV_SMEM);
    cudaFuncSetAttribute(k_oproj,  cudaFuncAttributeMaxDynamicSharedMemorySize, HG_SMEM);
    cudaFuncSetAttribute(k_conv1,  cudaFuncAttributeMaxDynamicSharedMemorySize, HG_SMEM);
    cudaFuncSetAttribute(k_conv2,  cudaFuncAttributeMaxDynamicSharedMemorySize, HG_SMEM);

    float* x2_d;
    cudaGetSymbolAddress((void**)&x2_d, g_x2);
    __nv_bfloat16 *wqh, *wql, *woh, *wol, *w1h, *w1l, *w2h, *w2l, *qih, *qil, *hlh, *hll;
    cudaGetSymbolAddress((void**)&wqh, g_wqkvh);  cudaGetSymbolAddress((void**)&wql, g_wqkvl);
    cudaGetSymbolAddress((void**)&woh, g_woh);    cudaGetSymbolAddress((void**)&wol, g_wol);
    cudaGetSymbolAddress((void**)&w1h, g_w1h);    cudaGetSymbolAddress((void**)&w1l, g_w1l);
    cudaGetSymbolAddress((void**)&w2h, g_w2h);    cudaGetSymbolAddress((void**)&w2l, g_w2l);
    cudaGetSymbolAddress((void**)&qih, g_qinh);   cudaGetSymbolAddress((void**)&qil, g_qinl);
    cudaGetSymbolAddress((void**)&hlh, g_hlnh);   cudaGetSymbolAddress((void**)&hll, g_hlnl);

    detect_mask_kernel<<<1, 1>>>((const unsigned char*)mask);
    // weight prep (every launch; deterministic)
    split_plain<<<(3 * D * D + 255) / 256, 256>>>(w_qkv, wqh, wql, 3 * D * D);
    split_plain<<<(D * D + 255) / 256, 256>>>(w_o, woh, wol, D * D);
    split_w_k3<<<(F * D + 255) / 256, 256>>>(w1, w1h, w1l, F, D);
    split_w_k3<<<(D * F + 255) / 256, 256>>>(w2, w2h, w2l, D, F);
    zero_pads<<<(4 * F + 255) / 256, 256>>>();

    // attention (all GEMMs on HMMA)
    ln_split<<<BT, 256>>>(x, ln1g, ln1b, pos, qih, qil, 0);
    k_qkv<<<dim3(3 * D / 128, BT / 128), 256, HG_SMEM>>>();
    transpose_v<<<dim3(T / 32, DH / 32, Bsz * H), dim3(32, 32)>>>();
    k_scores<<<dim3(T / 128, T / 128, Bsz * H), 256, HG_SMEM>>>();
    softmax_kernel<<<Bsz * H * T, 256>>>(mask);
    k_pv<<<dim3(1, T / 128, Bsz * H), 256, PV_SMEM>>>();
    k_oproj<<<dim3(D / 128, BT / 128), 256, HG_SMEM>>>(x);

    // conv block
    ln_split<<<BT, 256>>>(x2_d, ln2g, ln2b, nullptr, hlh, hll, 1);
    k_conv1<<<dim3(F / 128, BT / 128), 256, HG_SMEM>>>();
    k_conv2<<<dim3(D / 128, BT / 128), 256, HG_SMEM>>>(out);
}